// round 15
// baseline (speedup 1.0000x reference)
#include <cuda_runtime.h>
#include <math.h>

#define BB 4
#define NN 5
#define KK 5
#define QQ 5
#define LL 128
#define FF 768
#define NQv (NN*QQ)              // 25
#define BQ  (BB*NQv)             // 100
#define EPSF 1e-8f
#define PRED_ELEMS (BB*NQv*LL)   // 12800
#define ZSPLIT 4
#define ROWS_PER_Z (KK*LL/ZSPLIT)   // 160
#define LSEG 8
#define LPB (LL/LSEG)               // 16 l-rows per token block
#define YCH (FF/128)                // 6 f-chunks
#define FV  (FF/4)                  // 192 float4 per row
#define PROTO_BLOCKS (BB*NN*YCH*ZSPLIT)   // 480
#define FYCNT (BB*NN*YCH)                 // 120 finalize units

// Scratch (no cudaMalloc allowed). Counters self-reset each replay.
__device__ __align__(16) float g_proto[BB*NN*4*FF];
__device__ __align__(16) float g_partial[ZSPLIT*BB*NN*4*FF];
__device__ __align__(16) float g_sentproto[BB*NN*FF];
__device__ float g_p2p[YCH*BB*NN*4];
__device__ int   g_denp[YCH*ZSPLIT*BB*NN*4];
__device__ int   g_cnt1[BB*NN*YCH];
__device__ int   g_cnt2[BQ];
__device__ int   g_done;                 // proto finalize count (reset each replay)
__device__ int   g_fin;                  // bq finalize count (reset each replay)
__device__ int   g_sentpred[BQ];
__device__ float g_bce[BQ];
__device__ float g_segv[BQ*LSEG*4];
__device__ int   g_segi[BQ*LSEG*4];
__device__ float g_scratch[PRED_ELEMS + 4];

// ---------------------------------------------------------------------------
// ONE kernel: proto phase (blocks 0..479) -> device-wide flag -> token phase.
// grid = 800 linear blocks, 256 threads. All blocks resident (<=888 capacity).
// ---------------------------------------------------------------------------
__global__ void __launch_bounds__(256, 6)
mega_kernel(const float* __restrict__ sup,
            const float* __restrict__ qemb,
            const int*   __restrict__ sem,
            const int*   __restrict__ qem,
            const int*   __restrict__ sam,
            const int*   __restrict__ qatt,
            const int*   __restrict__ slab,
            float* loss_ptr,
            float* pred_out) {
    const int bx   = blockIdx.x;
    const int tid  = threadIdx.x;
    const int wid  = tid >> 5, lane = tid & 31;
    const int bq   = bx >> 3;          // 0..99
    const int s    = bx & 7;           // 0..7
    const int b    = bq / NQv;

    // proto smem
    __shared__ signed char s_cls[ROWS_PER_Z];
    __shared__ float  s_part[2][4][128];
    __shared__ int    s_den[4];
    __shared__ float  s_pp[4][4];
    __shared__ int    s_lastp;
    // token smem
    __shared__ float4 s_proto[4 * FV];
    __shared__ float  s_p2[4];
    __shared__ float  s_ml[LPB * 4];
    __shared__ float  s_wb[8];
    __shared__ float  s_red[8][NN];
    __shared__ int    s_last;
    __shared__ int    s_idx[4];
    __shared__ float  s_att[4];

    // ======== PHASE 1: proto (first 480 blocks) ========
    if (bx < PROTO_BLOCKS) {
        const int z     = bx / (BB*NN*YCH);     // 0..3
        const int y     = (bx / (BB*NN)) % YCH; // 0..5
        const int bn    = bx % (BB*NN);         // 0..19
        const int fbase = y * 128;
        const int fl    = tid & 127;
        const int grp   = tid >> 7;             // 0..1
        const int f     = fbase + fl;
        const int r0    = z * ROWS_PER_Z;

        if (bx == 0) {                          // fold init into one block
            if (tid == 0) *loss_ptr = 0.f;
            if (tid < BQ) g_bce[tid] = 0.f;
        }
        if (tid < 4) s_den[tid] = 0;
        __syncthreads();

        const int mbase = bn * KK * LL + r0;
        for (int i = tid; i < ROWS_PER_Z; i += 256) {
            int lab = sem[mbase + i];
            int att = sam[mbase + i];
            int c = (lab >= 1 && lab <= 4 && att > 0) ? (lab - 1) : -1;
            s_cls[i] = (signed char)c;
            if (c >= 0) atomicAdd(&s_den[c], 1);
        }
        __syncthreads();
        if (tid < 4)
            g_denp[(((y*ZSPLIT + z)*BB*NN) + bn)*4 + tid] = s_den[tid];

        const float* p = sup + (size_t)(bn * KK * LL + r0) * FF + f;
        float a0 = 0.f, a1 = 0.f, a2 = 0.f, a3 = 0.f;
        #pragma unroll 8
        for (int i = grp; i < ROWS_PER_Z; i += 2) {
            int c = s_cls[i];
            float v = __ldg(p + (size_t)i * FF);
            a0 += (c == 0) ? v : 0.f;
            a1 += (c == 1) ? v : 0.f;
            a2 += (c == 2) ? v : 0.f;
            a3 += (c == 3) ? v : 0.f;
        }
        s_part[grp][0][fl] = a0;
        s_part[grp][1][fl] = a1;
        s_part[grp][2][fl] = a2;
        s_part[grp][3][fl] = a3;
        __syncthreads();

        if (tid < 128) {
            int obase = ((z*BB*NN + bn) * 4) * FF + fbase + tid;
            #pragma unroll
            for (int c = 0; c < 4; c++)
                g_partial[obase + c*FF] = s_part[0][c][tid] + s_part[1][c][tid];
        }
        __threadfence();
        if (tid == 0)
            s_lastp = (atomicAdd(&g_cnt1[bn*YCH + y], 1) == ZSPLIT - 1) ? 1 : 0;
        __syncthreads();

        if (s_lastp) {   // last z-arriver for (bn,y): normalize + p2 + sentproto
            float pv0 = 0.f, pv1 = 0.f, pv2 = 0.f, pv3 = 0.f;
            if (tid < 128) {
                const int ff = fbase + tid;
                float vals[4];
                #pragma unroll
                for (int c = 0; c < 4; c++) {
                    int den = 0;
                    #pragma unroll
                    for (int zz = 0; zz < ZSPLIT; zz++)
                        den += g_denp[(((y*ZSPLIT + zz)*BB*NN) + bn)*4 + c];
                    int idx = ((bn * 4) + c) * FF + ff;
                    float sm = 0.f;
                    #pragma unroll
                    for (int zz = 0; zz < ZSPLIT; zz++)
                        sm += g_partial[(zz*BB*NN*4)*FF + idx];
                    float val = sm / ((float)den + EPSF);
                    g_proto[idx] = val;
                    vals[c] = val;
                }
                pv0 = vals[0]*vals[0]; pv1 = vals[1]*vals[1];
                pv2 = vals[2]*vals[2]; pv3 = vals[3]*vals[3];
                float sp = 0.f;
                const float* ps = sup + (size_t)bn * (KK*LL*FF) + ff;
                #pragma unroll
                for (int k = 0; k < KK; k++) sp += __ldg(ps + (size_t)k * LL * FF);
                g_sentproto[bn*FF + ff] = sp * (1.0f / (float)KK);
            }
            #pragma unroll
            for (int off = 16; off > 0; off >>= 1) {
                pv0 += __shfl_xor_sync(0xffffffffu, pv0, off);
                pv1 += __shfl_xor_sync(0xffffffffu, pv1, off);
                pv2 += __shfl_xor_sync(0xffffffffu, pv2, off);
                pv3 += __shfl_xor_sync(0xffffffffu, pv3, off);
            }
            if (lane == 0 && wid < 4) {
                s_pp[wid][0] = pv0; s_pp[wid][1] = pv1;
                s_pp[wid][2] = pv2; s_pp[wid][3] = pv3;
            }
            __syncthreads();
            if (tid < 4) {
                float pp = s_pp[0][tid] + s_pp[1][tid] + s_pp[2][tid] + s_pp[3][tid];
                g_p2p[(y*BB*NN + bn)*4 + tid] = pp;
            }
            __threadfence();
            __syncthreads();
            if (tid == 0) {
                g_cnt1[bn*YCH + y] = 0;      // reset for next replay
                atomicAdd(&g_done, 1);       // release proto unit
            }
        }
    }

    // ======== prefetch + q2 (overlaps with proto phase of other blocks) =====
    const int cond = slab[bq];
    const int bncond = b*NN + cond;
    const float4* qbase = (const float4*)(qemb + (size_t)bq * LL * FF);
    const int mlbase = bq * LL;
    const int lA = s * LPB + wid;
    const int lB = lA + 8;
    const float4* qrA = qbase + lA * FV;
    const float4* qrB = qbase + lB * FV;
    const float attA = (float)qatt[mlbase + lA];
    const float attB = (float)qatt[mlbase + lB];
    const int   emA  = qem[mlbase + lA];
    const int   emB  = qem[mlbase + lB];

    float q2a = 0.f, q2b = 0.f;
    #pragma unroll
    for (int j = 0; j < FV/32; j++) {
        int o = lane + 32*j;
        float4 va = __ldg(qrA + o);
        float4 vb = __ldg(qrB + o);
        q2a += va.x*va.x + va.y*va.y + va.z*va.z + va.w*va.w;
        q2b += vb.x*vb.x + vb.y*vb.y + vb.z*vb.z + vb.w*vb.w;
    }
    #pragma unroll
    for (int off = 16; off > 0; off >>= 1) {
        q2a += __shfl_xor_sync(0xffffffffu, q2a, off);
        q2b += __shfl_xor_sync(0xffffffffu, q2b, off);
    }

    // ======== wait for all protos ========
    if (tid == 0) {
        while (*(volatile int*)&g_done < FYCNT) __nanosleep(64);
    }
    __syncthreads();
    __threadfence();

    // ======== PHASE 2: token (R10 loop, q2 precomputed, q in L2) ========
    const float4* gp = (const float4*)(g_proto + (size_t)(bncond * 4) * FF);
    for (int i = tid; i < 4 * FV; i += 256) s_proto[i] = __ldg(gp + i);
    if (tid < 4) {
        float p = 0.f;
        #pragma unroll
        for (int y = 0; y < YCH; y++) p += g_p2p[(y*BB*NN + bncond)*4 + tid];
        s_p2[tid] = p;
    }
    __syncthreads();

    float bce_acc = 0.f;
    #pragma unroll
    for (int r = 0; r < 2; r++) {
        const int ll = r * 8 + wid;
        const float4* qr = (r == 0) ? qrA : qrB;
        const float q2  = (r == 0) ? q2a : q2b;
        const float att = (r == 0) ? attA : attB;
        const int   em  = (r == 0) ? emA  : emB;
        float c0 = 0.f, c1 = 0.f, c2 = 0.f, c3 = 0.f;
        #pragma unroll
        for (int j = 0; j < FV/32; j++) {
            int o = lane + 32*j;
            float4 v  = __ldg(qr + o);
            float4 w0 = s_proto[0*FV + o];
            float4 w1 = s_proto[1*FV + o];
            float4 w2 = s_proto[2*FV + o];
            float4 w3 = s_proto[3*FV + o];
            c0 += v.x*w0.x + v.y*w0.y + v.z*w0.z + v.w*w0.w;
            c1 += v.x*w1.x + v.y*w1.y + v.z*w1.z + v.w*w1.w;
            c2 += v.x*w2.x + v.y*w2.y + v.z*w2.z + v.w*w2.w;
            c3 += v.x*w3.x + v.y*w3.y + v.z*w3.z + v.w*w3.w;
        }
        #pragma unroll
        for (int off = 16; off > 0; off >>= 1) {
            c0 += __shfl_xor_sync(0xffffffffu, c0, off);
            c1 += __shfl_xor_sync(0xffffffffu, c1, off);
            c2 += __shfl_xor_sync(0xffffffffu, c2, off);
            c3 += __shfl_xor_sync(0xffffffffu, c3, off);
        }
        float tl[4];
        tl[0] = -(q2 + s_p2[0] - 2.f*c0);
        tl[1] = -(q2 + s_p2[1] - 2.f*c1);
        tl[2] = -(q2 + s_p2[2] - 2.f*c2);
        tl[3] = -(q2 + s_p2[3] - 2.f*c3);
        float bl = 0.f;
        #pragma unroll
        for (int c = 0; c < 4; c++) {
            float x = tl[c];
            float t = (em == c + 1) ? 1.f : 0.f;
            bl += fmaxf(x, 0.f) - x * t + log1pf(expf(-fabsf(x)));
        }
        bce_acc += bl * att;
        if (lane < 4) s_ml[ll*4 + lane] = tl[lane] - 1000.f * (1.f - att);
    }

    if (lane == 0) s_wb[wid] = bce_acc;
    __syncthreads();

    if (tid == 0) {
        float bs = 0.f;
        #pragma unroll
        for (int w = 0; w < 8; w++) bs += s_wb[w];
        atomicAdd(&g_bce[bq], bs);
    }
    if (tid < 4) {   // per-class first-occurrence argmax over this block's rows
        float best = s_ml[0*4 + tid]; int bi = 0;
        #pragma unroll
        for (int ll = 1; ll < LPB; ll++) {
            float v = s_ml[ll*4 + tid];
            if (v > best) { best = v; bi = ll; }
        }
        g_segv[(bq*LSEG + s)*4 + tid] = best;
        g_segi[(bq*LSEG + s)*4 + tid] = s * LPB + bi;
    }

    // -------- fused sentence path (one block per bq) --------
    if (s == 0) {
        const float* qrow = qemb + (size_t)bq * LL * FF;
        float d2[NN];
        #pragma unroll
        for (int n = 0; n < NN; n++) d2[n] = 0.f;
        for (int f = tid; f < FF; f += 256) {
            float qv = __ldg(qrow + f);
            #pragma unroll
            for (int n = 0; n < NN; n++) {
                float d = g_sentproto[(b*NN + n)*FF + f] - qv;
                d2[n] += d * d;
            }
        }
        #pragma unroll
        for (int off = 16; off > 0; off >>= 1)
            #pragma unroll
            for (int n = 0; n < NN; n++)
                d2[n] += __shfl_xor_sync(0xffffffffu, d2[n], off);
        if (lane == 0)
            #pragma unroll
            for (int n = 0; n < NN; n++) s_red[wid][n] = d2[n];
        __syncthreads();
        if (tid == 0) {
            float lg[NN];
            #pragma unroll
            for (int n = 0; n < NN; n++) {
                float sm = 0.f;
                #pragma unroll
                for (int w = 0; w < 8; w++) sm += s_red[w][n];
                lg[n] = -sm;
            }
            float mx = lg[0]; int am = 0;
            #pragma unroll
            for (int n = 1; n < NN; n++) if (lg[n] > mx) { mx = lg[n]; am = n; }
            float se = 0.f;
            #pragma unroll
            for (int n = 0; n < NN; n++) se += expf(lg[n] - mx);
            float logp = lg[cond] - mx - logf(se);
            atomicAdd(loss_ptr, -logp / (float)BQ);
            g_sentpred[bq] = am;
        }
    }

    // -------- last-block finalize for this bq --------
    __threadfence();
    if (tid == 0)
        s_last = (atomicAdd(&g_cnt2[bq], 1) == LSEG - 1) ? 1 : 0;
    __syncthreads();
    if (!s_last) return;

    if (tid < 4) {   // merge segments in order; strict > keeps first occurrence
        float best = g_segv[(bq*LSEG + 0)*4 + tid];
        int   bi   = g_segi[(bq*LSEG + 0)*4 + tid];
        #pragma unroll
        for (int ss = 1; ss < LSEG; ss++) {
            float v = g_segv[(bq*LSEG + ss)*4 + tid];
            if (v > best) { best = v; bi = g_segi[(bq*LSEG + ss)*4 + tid]; }
        }
        s_idx[tid] = bi;
    }
    if (tid < LL) {
        float a = (float)qatt[mlbase + tid];
        #pragma unroll
        for (int off = 16; off > 0; off >>= 1) a += __shfl_xor_sync(0xffffffffu, a, off);
        if (lane == 0) s_att[wid] = a;
    }
    __syncthreads();

    if (tid == 0) {
        float as = s_att[0] + s_att[1] + s_att[2] + s_att[3];
        float per = g_bce[bq] / (as * 4.f + EPSF);
        atomicAdd(loss_ptr, per / (float)BQ);
        g_cnt2[bq] = 0;
        g_bce[bq]  = 0.f;
        if (atomicAdd(&g_fin, 1) == BQ - 1) {   // very last bq finalizer
            g_fin  = 0;
            g_done = 0;                          // reset for next replay
        }
    }
    if (tid < LL) {
        int pos = tid;
        int i0 = s_idx[0], i1 = s_idx[1], i2 = s_idx[2], i3 = s_idx[3];
        int pred = 0;
        if (pos == i0)             pred = 1;
        if (pos > i0 && pos <= i1) pred = 2;
        if (pos == i2)             pred = 3;
        if (pos > i2 && pos <= i3) pred = 4;
        int sp = g_sentpred[bq];
        pred_out[mlbase + tid] = (float)((pred != 0) ? (4*sp + pred) : 0);
    }
}

// ---------------------------------------------------------------------------
extern "C" void kernel_launch(void* const* d_in, const int* in_sizes, int n_in,
                              void* d_out, int out_size) {
    const float* sup  = (const float*)d_in[0];
    const float* qemb = (const float*)d_in[1];
    const int*   sem  = (const int*)d_in[2];
    const int*   qem  = (const int*)d_in[3];
    const int*   sam  = (const int*)d_in[4];
    const int*   qatt = (const int*)d_in[5];
    const int*   slab = (const int*)d_in[6];

    float* out = (float*)d_out;
    float* scratch = nullptr;
    cudaGetSymbolAddress((void**)&scratch, g_scratch);

    float* loss_ptr;
    float* pred_ptr;
    if (out_size >= PRED_ELEMS + 1) {
        loss_ptr = out;
        pred_ptr = out + 1;
    } else if (out_size == PRED_ELEMS) {
        loss_ptr = scratch + PRED_ELEMS;
        pred_ptr = out;
    } else {
        loss_ptr = out;
        pred_ptr = scratch;
    }

    mega_kernel<<<BQ*LSEG, 256>>>(sup, qemb, sem, qem, sam, qatt, slab,
                                  loss_ptr, pred_ptr);
}

// round 16
// speedup vs baseline: 1.1249x; 1.1249x over previous
#include <cuda_runtime.h>
#include <math.h>

#define BB 4
#define NN 5
#define KK 5
#define QQ 5
#define LL 128
#define FF 768
#define NQv (NN*QQ)              // 25
#define BQ  (BB*NQv)             // 100
#define EPSF 1e-8f
#define PRED_ELEMS (BB*NQv*LL)   // 12800
#define ZSPLIT 4
#define ROWS_PER_Z (KK*LL/ZSPLIT)   // 160
#define LSEG 8
#define LPB (LL/LSEG)               // 16 l-rows per token block
#define YCH (FF/128)                // 6 f-chunks
#define FV  (FF/4)                  // 192 float4 per row

// Scratch (no cudaMalloc allowed). Counters self-reset each replay.
__device__ __align__(16) float g_proto[BB*NN*4*FF];
__device__ __align__(16) float g_partial[ZSPLIT*BB*NN*4*FF];
__device__ __align__(16) float g_sentproto[BB*NN*FF];
__device__ float g_p2p[YCH*BB*NN*4];              // per-chunk proto^2 partials
__device__ int   g_denp[YCH*ZSPLIT*BB*NN*4];
__device__ int   g_cnt1[BB*NN*YCH];
__device__ int   g_cnt2[BQ];
__device__ int   g_sentpred[BQ];
__device__ float g_bce[BQ];
__device__ float g_segv[BQ*LSEG*4];
__device__ int   g_segi[BQ*LSEG*4];
__device__ float g_scratch[PRED_ELEMS + 4];

// ---------------------------------------------------------------------------
// Kernel 1: proto partials (branchless) + dens; last z-block per (bn,y)
// normalizes its f-chunk, computes p2 chunk partials, sentence protos.
// grid=(B*N, YCH, ZSPLIT), block=512.  (R10-proven version)
// ---------------------------------------------------------------------------
__global__ void proto_fused_kernel(const float* __restrict__ sup,
                                   const int*   __restrict__ sem,
                                   const int*   __restrict__ sam,
                                   float* loss_ptr) {
    const int bn    = blockIdx.x;
    const int y     = blockIdx.y;
    const int z     = blockIdx.z;
    const int fbase = y * 128;
    const int tid   = threadIdx.x;
    const int fl    = tid & 127;
    const int grp   = tid >> 7;
    const int lane  = tid & 31;
    const int wid   = tid >> 5;
    const int f     = fbase + fl;
    const int r0    = z * ROWS_PER_Z;

    __shared__ signed char s_cls[ROWS_PER_Z];
    __shared__ float s_part[4][4][128];
    __shared__ int   s_den[4];
    __shared__ int   s_last;
    __shared__ float s_pp[4][4];

    if (bn == 0 && y == 0 && z == 0 && tid == 0) *loss_ptr = 0.f;
    if (tid < 4) s_den[tid] = 0;
    __syncthreads();

    const int mbase = bn * KK * LL + r0;
    for (int i = tid; i < ROWS_PER_Z; i += 512) {
        int lab = sem[mbase + i];
        int att = sam[mbase + i];
        int c = (lab >= 1 && lab <= 4 && att > 0) ? (lab - 1) : -1;
        s_cls[i] = (signed char)c;
        if (c >= 0) atomicAdd(&s_den[c], 1);
    }
    __syncthreads();

    if (tid < 4)
        g_denp[(((y*ZSPLIT + z)*BB*NN) + bn)*4 + tid] = s_den[tid];

    const float* p = sup + (size_t)(bn * KK * LL + r0) * FF + f;
    float a0 = 0.f, a1 = 0.f, a2 = 0.f, a3 = 0.f;
    #pragma unroll 8
    for (int i = grp; i < ROWS_PER_Z; i += 4) {
        int c = s_cls[i];
        float v = __ldg(p + (size_t)i * FF);
        a0 += (c == 0) ? v : 0.f;
        a1 += (c == 1) ? v : 0.f;
        a2 += (c == 2) ? v : 0.f;
        a3 += (c == 3) ? v : 0.f;
    }
    s_part[grp][0][fl] = a0;
    s_part[grp][1][fl] = a1;
    s_part[grp][2][fl] = a2;
    s_part[grp][3][fl] = a3;
    __syncthreads();

    if (tid < 128) {
        int obase = ((z*BB*NN + bn) * 4) * FF + fbase + tid;
        #pragma unroll
        for (int c = 0; c < 4; c++) {
            g_partial[obase + c*FF] =
                s_part[0][c][tid] + s_part[1][c][tid] +
                s_part[2][c][tid] + s_part[3][c][tid];
        }
    }
    __threadfence();
    if (tid == 0)
        s_last = (atomicAdd(&g_cnt1[bn*YCH + y], 1) == ZSPLIT - 1) ? 1 : 0;
    __syncthreads();

    if (s_last) {   // last arriver for (bn,y): normalize chunk + p2 partials
        float pv0 = 0.f, pv1 = 0.f, pv2 = 0.f, pv3 = 0.f;
        if (tid < 128) {
            const int ff = fbase + tid;
            float vals[4];
            #pragma unroll
            for (int c = 0; c < 4; c++) {
                int den = 0;
                #pragma unroll
                for (int zz = 0; zz < ZSPLIT; zz++)
                    den += g_denp[(((y*ZSPLIT + zz)*BB*NN) + bn)*4 + c];
                int idx = ((bn * 4) + c) * FF + ff;
                float s = 0.f;
                #pragma unroll
                for (int zz = 0; zz < ZSPLIT; zz++)
                    s += g_partial[(zz*BB*NN*4)*FF + idx];
                float val = s / ((float)den + EPSF);
                g_proto[idx] = val;
                vals[c] = val;
            }
            pv0 = vals[0]*vals[0]; pv1 = vals[1]*vals[1];
            pv2 = vals[2]*vals[2]; pv3 = vals[3]*vals[3];
            float sp = 0.f;
            const float* ps = sup + (size_t)bn * (KK*LL*FF) + ff;
            #pragma unroll
            for (int k = 0; k < KK; k++) sp += __ldg(ps + (size_t)k * LL * FF);
            g_sentproto[bn*FF + ff] = sp * (1.0f / (float)KK);
        }
        #pragma unroll
        for (int off = 16; off > 0; off >>= 1) {
            pv0 += __shfl_xor_sync(0xffffffffu, pv0, off);
            pv1 += __shfl_xor_sync(0xffffffffu, pv1, off);
            pv2 += __shfl_xor_sync(0xffffffffu, pv2, off);
            pv3 += __shfl_xor_sync(0xffffffffu, pv3, off);
        }
        if (lane == 0 && wid < 4) {
            s_pp[wid][0] = pv0; s_pp[wid][1] = pv1;
            s_pp[wid][2] = pv2; s_pp[wid][3] = pv3;
        }
        __syncthreads();
        if (tid < 4) {
            float pp = s_pp[0][tid] + s_pp[1][tid] + s_pp[2][tid] + s_pp[3][tid];
            g_p2p[(y*BB*NN + bn)*4 + tid] = pp;
        }
        if (tid == 0) g_cnt1[bn*YCH + y] = 0;   // reset for next replay
    }
}

// ---------------------------------------------------------------------------
// Kernel 2: grid=(BQ, LSEG+1), 256 threads.
//   s < LSEG : R10 token block (uniform work, 16 rows, smem proto).
//   s == LSEG: dedicated sentence block (log-softmax loss + sent pred).
// All LSEG+1 blocks per bq join the completion count; 9th arriver finalizes.
// ---------------------------------------------------------------------------
__global__ void __launch_bounds__(256)
token_fused_kernel(const float* __restrict__ qemb,
                   const int*   __restrict__ qem,
                   const int*   __restrict__ qatt,
                   const int*   __restrict__ slab,
                   float* loss_ptr,
                   float* pred_out) {
    const int bq   = blockIdx.x;
    const int s    = blockIdx.y;           // 0..LSEG  (LSEG = sentence block)
    const int b    = bq / NQv;
    const int tid  = threadIdx.x;
    const int wid  = tid >> 5, lane = tid & 31;

    __shared__ float4 s_proto[4 * FV];
    __shared__ float  s_p2[4];
    __shared__ float  s_ml[LPB * 4];
    __shared__ float  s_wb[8];
    __shared__ float  s_red[8][NN];
    __shared__ int    s_last;
    __shared__ int    s_idx[4];
    __shared__ float  s_att[4];

    const int cond = slab[bq];
    const int bncond = b*NN + cond;
    const int mlbase = bq * LL;

    if (s < LSEG) {
        // ---------------- token block (R10-exact loop) ----------------
        const float4* gp = (const float4*)(g_proto + (size_t)(bncond * 4) * FF);
        for (int i = tid; i < 4 * FV; i += 256) s_proto[i] = __ldg(gp + i);
        if (tid < 4) {  // p2 from deterministic per-chunk partials
            float p = 0.f;
            #pragma unroll
            for (int y = 0; y < YCH; y++) p += g_p2p[(y*BB*NN + bncond)*4 + tid];
            s_p2[tid] = p;
        }
        __syncthreads();

        const float4* qbase = (const float4*)(qemb + (size_t)bq * LL * FF);
        float bce_acc = 0.f;

        #pragma unroll
        for (int r = 0; r < 2; r++) {
            const int ll = r * 8 + wid;       // 0..15 local
            const int l  = s * LPB + ll;      // global l
            const float4* qr = qbase + l * FV;
            // hoisted so scalar loads overlap the vector stream
            const float att = (float)qatt[mlbase + l];
            const int   em  = qem[mlbase + l];
            float q2 = 0.f, c0 = 0.f, c1 = 0.f, c2 = 0.f, c3 = 0.f;
            #pragma unroll
            for (int j = 0; j < FV/32; j++) {
                int o = lane + 32*j;
                float4 v  = __ldg(qr + o);
                float4 w0 = s_proto[0*FV + o];
                float4 w1 = s_proto[1*FV + o];
                float4 w2 = s_proto[2*FV + o];
                float4 w3 = s_proto[3*FV + o];
                q2 += v.x*v.x + v.y*v.y + v.z*v.z + v.w*v.w;
                c0 += v.x*w0.x + v.y*w0.y + v.z*w0.z + v.w*w0.w;
                c1 += v.x*w1.x + v.y*w1.y + v.z*w1.z + v.w*w1.w;
                c2 += v.x*w2.x + v.y*w2.y + v.z*w2.z + v.w*w2.w;
                c3 += v.x*w3.x + v.y*w3.y + v.z*w3.z + v.w*w3.w;
            }
            #pragma unroll
            for (int off = 16; off > 0; off >>= 1) {
                q2 += __shfl_xor_sync(0xffffffffu, q2, off);
                c0 += __shfl_xor_sync(0xffffffffu, c0, off);
                c1 += __shfl_xor_sync(0xffffffffu, c1, off);
                c2 += __shfl_xor_sync(0xffffffffu, c2, off);
                c3 += __shfl_xor_sync(0xffffffffu, c3, off);
            }
            float tl[4];
            tl[0] = -(q2 + s_p2[0] - 2.f*c0);
            tl[1] = -(q2 + s_p2[1] - 2.f*c1);
            tl[2] = -(q2 + s_p2[2] - 2.f*c2);
            tl[3] = -(q2 + s_p2[3] - 2.f*c3);
            float bl = 0.f;
            #pragma unroll
            for (int c = 0; c < 4; c++) {
                float x = tl[c];
                float t = (em == c + 1) ? 1.f : 0.f;
                bl += fmaxf(x, 0.f) - x * t + log1pf(expf(-fabsf(x)));
            }
            bce_acc += bl * att;
            if (lane < 4) s_ml[ll*4 + lane] = tl[lane] - 1000.f * (1.f - att);
        }

        if (lane == 0) s_wb[wid] = bce_acc;
        __syncthreads();

        if (tid == 0) {
            float bs = 0.f;
            #pragma unroll
            for (int w = 0; w < 8; w++) bs += s_wb[w];
            atomicAdd(&g_bce[bq], bs);
        }
        if (tid < 4) {   // per-class first-occurrence argmax over 16 rows
            float best = s_ml[0*4 + tid]; int bi = 0;
            #pragma unroll
            for (int ll = 1; ll < LPB; ll++) {
                float v = s_ml[ll*4 + tid];
                if (v > best) { best = v; bi = ll; }
            }
            g_segv[(bq*LSEG + s)*4 + tid] = best;
            g_segi[(bq*LSEG + s)*4 + tid] = s * LPB + bi;
        }
    } else {
        // ---------------- dedicated sentence block ----------------
        const float* qrow = qemb + (size_t)bq * LL * FF;   // l = 0 row
        float d2[NN];
        #pragma unroll
        for (int n = 0; n < NN; n++) d2[n] = 0.f;
        for (int f = tid; f < FF; f += 256) {
            float qv = __ldg(qrow + f);
            #pragma unroll
            for (int n = 0; n < NN; n++) {
                float d = g_sentproto[(b*NN + n)*FF + f] - qv;
                d2[n] += d * d;
            }
        }
        #pragma unroll
        for (int off = 16; off > 0; off >>= 1)
            #pragma unroll
            for (int n = 0; n < NN; n++)
                d2[n] += __shfl_xor_sync(0xffffffffu, d2[n], off);
        if (lane == 0)
            #pragma unroll
            for (int n = 0; n < NN; n++) s_red[wid][n] = d2[n];
        __syncthreads();
        if (tid == 0) {
            float lg[NN];
            #pragma unroll
            for (int n = 0; n < NN; n++) {
                float sm = 0.f;
                #pragma unroll
                for (int w = 0; w < 8; w++) sm += s_red[w][n];
                lg[n] = -sm;
            }
            float mx = lg[0]; int am = 0;
            #pragma unroll
            for (int n = 1; n < NN; n++) if (lg[n] > mx) { mx = lg[n]; am = n; }
            float se = 0.f;
            #pragma unroll
            for (int n = 0; n < NN; n++) se += expf(lg[n] - mx);
            float logp = lg[cond] - mx - logf(se);
            atomicAdd(loss_ptr, -logp / (float)BQ);
            g_sentpred[bq] = am;
        }
    }

    // -------- last-arriver finalize for this bq (LSEG+1 participants) --------
    __threadfence();
    if (tid == 0)
        s_last = (atomicAdd(&g_cnt2[bq], 1) == LSEG) ? 1 : 0;   // 9th arriver
    __syncthreads();
    if (!s_last) return;

    if (tid < 4) {   // merge segments in order; strict > keeps first occurrence
        float best = g_segv[(bq*LSEG + 0)*4 + tid];
        int   bi   = g_segi[(bq*LSEG + 0)*4 + tid];
        #pragma unroll
        for (int ss = 1; ss < LSEG; ss++) {
            float v = g_segv[(bq*LSEG + ss)*4 + tid];
            if (v > best) { best = v; bi = g_segi[(bq*LSEG + ss)*4 + tid]; }
        }
        s_idx[tid] = bi;
    }
    if (tid < LL) {
        float a = (float)qatt[mlbase + tid];
        #pragma unroll
        for (int off = 16; off > 0; off >>= 1) a += __shfl_xor_sync(0xffffffffu, a, off);
        if (lane == 0) s_att[wid] = a;
    }
    __syncthreads();

    if (tid == 0) {
        float as = s_att[0] + s_att[1] + s_att[2] + s_att[3];
        float per = g_bce[bq] / (as * 4.f + EPSF);
        atomicAdd(loss_ptr, per / (float)BQ);
        g_cnt2[bq] = 0;      // reset for next replay
        g_bce[bq]  = 0.f;    // reset for next replay
    }
    if (tid < LL) {
        int pos = tid;
        int i0 = s_idx[0], i1 = s_idx[1], i2 = s_idx[2], i3 = s_idx[3];
        int pred = 0;
        if (pos == i0)             pred = 1;
        if (pos > i0 && pos <= i1) pred = 2;
        if (pos == i2)             pred = 3;
        if (pos > i2 && pos <= i3) pred = 4;
        int sp = g_sentpred[bq];
        pred_out[mlbase + tid] = (float)((pred != 0) ? (4*sp + pred) : 0);
    }
}

// ---------------------------------------------------------------------------
extern "C" void kernel_launch(void* const* d_in, const int* in_sizes, int n_in,
                              void* d_out, int out_size) {
    const float* sup  = (const float*)d_in[0];
    const float* qemb = (const float*)d_in[1];
    const int*   sem  = (const int*)d_in[2];
    const int*   qem  = (const int*)d_in[3];
    const int*   sam  = (const int*)d_in[4];
    const int*   qatt = (const int*)d_in[5];
    const int*   slab = (const int*)d_in[6];

    float* out = (float*)d_out;
    float* scratch = nullptr;
    cudaGetSymbolAddress((void**)&scratch, g_scratch);

    float* loss_ptr;
    float* pred_ptr;
    if (out_size >= PRED_ELEMS + 1) {
        loss_ptr = out;
        pred_ptr = out + 1;
    } else if (out_size == PRED_ELEMS) {
        loss_ptr = scratch + PRED_ELEMS;
        pred_ptr = out;
    } else {
        loss_ptr = out;
        pred_ptr = scratch;
    }

    proto_fused_kernel<<<dim3(BB*NN, YCH, ZSPLIT), 512>>>(sup, sem, sam, loss_ptr);
    token_fused_kernel<<<dim3(BQ, LSEG + 1), 256>>>(qemb, qem, qatt, slab,
                                                    loss_ptr, pred_ptr);
}